// round 5
// baseline (speedup 1.0000x reference)
#include <cuda_runtime.h>
#include <cuda_bf16.h>
#include <math.h>
#include <stdint.h>

// ---------------------------------------------------------------------------
// Problem shapes (fixed)
// ---------------------------------------------------------------------------
#define BATCH 4
#define DIM 192
#define HEADS 8
#define HDIM 24
#define HH 256
#define WW 256
#define HWN 65536
#define QKV_CH 576

#define KEXT 576                     // 3 regions x 192 bf16 slots
#define WROW 288                     // u32 words per extended weight row
#define WCHUNKE (192 * WROW)         // u32 words per 192-row weight chunk

// ---------------------------------------------------------------------------
// Scratch (device globals: allocation-free rule)
// ---------------------------------------------------------------------------
__device__ float g_qkv[(size_t)BATCH * QKV_CH * HWN];
__device__ float g_v[(size_t)BATCH * DIM * HWN];
__device__ float g_spart[(size_t)BATCH * HEADS * 512 * 624];
__device__ float g_sred[BATCH * HEADS * 624];
__device__ float g_attn[BATCH * HEADS * HDIM * HDIM];
__device__ uint32_t g_wext[3 * WCHUNKE];        // qkv weights, 3-term ext rows
__device__ uint32_t g_Mext[BATCH * WCHUNKE];    // proj*blockdiag(attn), ext rows

// ---------------------------------------------------------------------------
// helpers
// ---------------------------------------------------------------------------
__device__ __forceinline__ void split_bf16(float v, uint16_t& h, uint16_t& l) {
    __nv_bfloat16 bh = __float2bfloat16(v);
    float r = v - __bfloat162float(bh);
    __nv_bfloat16 bl = __float2bfloat16(r);
    h = __bfloat16_as_ushort(bh);
    l = __bfloat16_as_ushort(bl);
}

__device__ __forceinline__ uint32_t smem_u32(const void* p) {
    uint32_t a;
    asm("{ .reg .u64 t; cvta.to.shared.u64 t, %1; cvt.u32.u64 %0, t; }" : "=r"(a) : "l"(p));
    return a;
}

__device__ __forceinline__ void mma16816(float* c, const uint32_t* a, const uint32_t* b) {
    asm volatile(
        "mma.sync.aligned.m16n8k16.row.col.f32.bf16.bf16.f32 "
        "{%0,%1,%2,%3}, {%4,%5,%6,%7}, {%8,%9}, {%0,%1,%2,%3};"
        : "+f"(c[0]), "+f"(c[1]), "+f"(c[2]), "+f"(c[3])
        : "r"(a[0]), "r"(a[1]), "r"(a[2]), "r"(a[3]), "r"(b[0]), "r"(b[1]));
}

#define LDSM4(r0, r1, r2, r3, addr) \
    asm volatile("ldmatrix.sync.aligned.m8n8.x4.shared.b16 {%0,%1,%2,%3}, [%4];" \
        : "=r"(r0), "=r"(r1), "=r"(r2), "=r"(r3) : "r"(addr))

// ---------------------------------------------------------------------------
// K0: split qkv weights -> extended bf16 rows [576 rows][576 slots]
// slot k = hi, 192+k = lo, 384+k = hi
// ---------------------------------------------------------------------------
__global__ __launch_bounds__(256)
void wprep_k(const float* __restrict__ w, uint32_t* __restrict__ wext)
{
    int idx = blockIdx.x * 256 + threadIdx.x;
    if (idx >= QKV_CH * DIM) return;
    int r = idx / DIM, k = idx % DIM;
    uint16_t h, l;
    split_bf16(w[idx], h, l);
    uint16_t* row = (uint16_t*)wext + (size_t)r * KEXT;
    row[k] = h;
    row[192 + k] = l;
    row[384 + k] = h;
}

// ---------------------------------------------------------------------------
// tgemm: C[m][px] = sum_c W[m][c] * src[c][px], mma.sync bf16 3-term split.
// Block: 512 threads (16 warps, 4x4), BM=192, BN=128 pixels, K_ext=576.
// B tile converted ONCE to resident SMEM hi/lo; all nchunk m-chunks reuse it.
// Fragment loads via ldmatrix.x4 (conflict-free: As stride 20, Bs stride 100).
// ---------------------------------------------------------------------------
#define AS_STR 20
#define BS_STR 100
#define TGEMM_SMEM ((192 * AS_STR + 2 * 128 * BS_STR) * 4)   // 117760 B

__global__ __launch_bounds__(512, 1)
void tgemm_k(const uint32_t* __restrict__ wext, const float* __restrict__ src,
             float* __restrict__ out, size_t wBS, size_t srcBS, size_t outBS,
             int nchunk)
{
    extern __shared__ uint32_t dsm[];
    uint32_t* As   = dsm;                        // [192][AS_STR]
    uint32_t* Bs_h = dsm + 192 * AS_STR;         // [128 px][BS_STR] (96 used)
    uint32_t* Bs_l = Bs_h + 128 * BS_STR;

    const int tid = threadIdx.x;
    const int wid = tid >> 5;
    const int lane = tid & 31;
    const int g = lane >> 2;
    const int tig = lane & 3;
    const int warpM = wid & 3;
    const int warpN = wid >> 2;

    const int p0 = blockIdx.x * 128;
    const int b = blockIdx.y;

    const uint32_t* wp0 = wext + (size_t)b * wBS;
    const float* sp = src + (size_t)b * srcBS + p0;

    // ---- phase 1: convert pixel tile -> resident Bs_h / Bs_l (once)
#pragma unroll
    for (int pass = 0; pass < 6; pass++) {
        int cpair = pass * 16 + wid;
        const float* r0 = sp + ((size_t)(2 * cpair) << 16);
        const float* r1 = sp + ((size_t)(2 * cpair + 1) << 16);
#pragma unroll
        for (int i = 0; i < 4; i++) {
            int px = lane + 32 * i;
            uint16_t h0, l0, h1, l1;
            split_bf16(__ldg(r0 + px), h0, l0);
            split_bf16(__ldg(r1 + px), h1, l1);
            Bs_h[px * BS_STR + cpair] = (uint32_t)h1 << 16 | h0;
            Bs_l[px * BS_STR + cpair] = (uint32_t)l1 << 16 | l0;
        }
    }

    // ---- ldmatrix per-lane address components
    const uint32_t As_u32  = smem_u32(As);
    const uint32_t BsH_u32 = smem_u32(Bs_h);
    const uint32_t BsL_u32 = smem_u32(Bs_l);
    // A: lanes 0-7 -> rows r0..r0+7 @kc; 8-15 -> +8 rows; 16-23 -> kc+4; 24-31 -> both
    const uint32_t aRow = warpM * 48 + (lane & 7) + ((lane >> 3) & 1) * 8;
    const uint32_t aOff = (aRow * AS_STR + (lane >> 4) * 4) * 4;
    // B: x4 covers nt pair: lanes 0-7 -> (nt=2p, kc), 8-15 -> (nt=2p, kc+4),
    //    16-23 -> (nt=2p+1, kc), 24-31 -> (nt=2p+1, kc+4)
    const uint32_t bRowOff =
        ((warpN * 32 + (lane >> 4) * 8 + (lane & 7)) * BS_STR + ((lane >> 3) & 1) * 4) * 4;

    // ---- A slab loader indices (192 rows x 16 u32 per slab)
    const int aM0 = tid >> 2;
    const int aM1 = 128 + (tid >> 2);
    const int aJ = (tid & 3) * 4;

    uint4 apf0, apf1;
    apf0 = *(const uint4*)(wp0 + (size_t)aM0 * WROW + aJ);
    if (tid < 256) apf1 = *(const uint4*)(wp0 + (size_t)aM1 * WROW + aJ);
    __syncthreads();   // Bs ready

    for (int chunk = 0; chunk < nchunk; chunk++) {
        float acc[3][4][4];
#pragma unroll
        for (int mt = 0; mt < 3; mt++)
#pragma unroll
            for (int nt = 0; nt < 4; nt++)
#pragma unroll
                for (int i = 0; i < 4; i++) acc[mt][nt][i] = 0.f;

        for (int it = 0; it < 18; it++) {
            // store A slab
            *(uint4*)&As[aM0 * AS_STR + aJ] = apf0;
            if (tid < 256) *(uint4*)&As[aM1 * AS_STR + aJ] = apf1;
            __syncthreads();

            // prefetch next slab (possibly next chunk's slab 0)
            {
                int nc = chunk, ni = it + 1;
                if (ni == 18) { ni = 0; nc++; }
                if (nc < nchunk) {
                    const uint32_t* wpn = wp0 + (size_t)nc * WCHUNKE + ni * 16;
                    apf0 = *(const uint4*)(wpn + (size_t)aM0 * WROW + aJ);
                    if (tid < 256) apf1 = *(const uint4*)(wpn + (size_t)aM1 * WROW + aJ);
                }
            }

            const uint32_t bSel = (it < 12) ? BsH_u32 : BsL_u32;
            const uint32_t bbase = (uint32_t)((it % 6) * 16) * 4;

#pragma unroll
            for (int ks = 0; ks < 2; ks++) {
                const uint32_t kcB = ks * 32;   // ks*8 words * 4B
                uint32_t afr[3][4], bfr[4][2];
#pragma unroll
                for (int mt = 0; mt < 3; mt++)
                    LDSM4(afr[mt][0], afr[mt][1], afr[mt][2], afr[mt][3],
                          As_u32 + aOff + (uint32_t)(mt * 16 * AS_STR) * 4 + kcB);
#pragma unroll
                for (int p = 0; p < 2; p++)
                    LDSM4(bfr[2 * p][0], bfr[2 * p][1], bfr[2 * p + 1][0], bfr[2 * p + 1][1],
                          bSel + bRowOff + (uint32_t)(p * 16 * BS_STR) * 4 + bbase + kcB);
#pragma unroll
                for (int mt = 0; mt < 3; mt++)
#pragma unroll
                    for (int nt = 0; nt < 4; nt++)
                        mma16816(acc[mt][nt], afr[mt], bfr[nt]);
            }
            __syncthreads();
        }

        // ---- epilogue for this chunk
        float* op = out + (size_t)b * outBS + ((size_t)chunk * 192 << 16);
#pragma unroll
        for (int mt = 0; mt < 3; mt++) {
#pragma unroll
            for (int nt = 0; nt < 4; nt++) {
                int row = warpM * 48 + mt * 16 + g;
                int col = p0 + warpN * 32 + nt * 8 + tig * 2;
                *(float2*)&op[((size_t)row << 16) + col] =
                    make_float2(acc[mt][nt][0], acc[mt][nt][1]);
                *(float2*)&op[((size_t)(row + 8) << 16) + col] =
                    make_float2(acc[mt][nt][2], acc[mt][nt][3]);
            }
        }
    }
}

// ---------------------------------------------------------------------------
// depthwise 3x3, SAME padding (scalar helper for dwgram)
// ---------------------------------------------------------------------------
__device__ __forceinline__ float dw3x3(const float* __restrict__ in,
                                       const float* __restrict__ w9,
                                       int y, int x)
{
    float s = 0.f;
#pragma unroll
    for (int dy = -1; dy <= 1; dy++) {
        int yy = y + dy;
        if (yy < 0 || yy > HH - 1) continue;
#pragma unroll
        for (int dx = -1; dx <= 1; dx++) {
            int xx = x + dx;
            if (xx < 0 || xx > WW - 1) continue;
            s = fmaf(w9[(dy + 1) * 3 + (dx + 1)], in[yy * WW + xx], s);
        }
    }
    return s;
}

// ---------------------------------------------------------------------------
// K2: fused dwconv (q,k) + Gram partials + norms
// ---------------------------------------------------------------------------
__global__ __launch_bounds__(192)
void dwgram_k(const float* __restrict__ qkv, const float* __restrict__ dww,
              float* __restrict__ spart)
{
    __shared__ float qs[24][132];
    __shared__ float ks[24][132];

    const int b = blockIdx.z, h = blockIdx.y;
    const int y = blockIdx.x >> 1;
    const int x0 = (blockIdx.x & 1) * 128;
    const int tid = threadIdx.x;

    for (int idx = tid; idx < 48 * 128; idx += 192) {
        int c = idx >> 7;
        int x = idx & 127;
        int ch = (c < 24) ? (h * 24 + c) : (192 + h * 24 + (c - 24));
        const float* in = qkv + ((size_t)(b * QKV_CH + ch) << 16);
        float v = dw3x3(in, dww + ch * 9, y, x0 + x);
        if (c < 24) qs[c][x] = v;
        else        ks[c - 24][x] = v;
    }
    __syncthreads();

    float* out = spart + ((size_t)(b * HEADS + h) * 512 + blockIdx.x) * 624;

    if (tid < 144) {
        int d = (tid / 12) * 2, e = (tid % 12) * 2;
        float a00 = 0, a01 = 0, a10 = 0, a11 = 0;
#pragma unroll 4
        for (int n = 0; n < 128; n++) {
            float q0 = qs[d][n], q1 = qs[d + 1][n];
            float k0 = ks[e][n], k1 = ks[e + 1][n];
            a00 = fmaf(q0, k0, a00); a01 = fmaf(q0, k1, a01);
            a10 = fmaf(q1, k0, a10); a11 = fmaf(q1, k1, a11);
        }
        out[d * 24 + e] = a00;
        out[d * 24 + e + 1] = a01;
        out[(d + 1) * 24 + e] = a10;
        out[(d + 1) * 24 + e + 1] = a11;
    } else if (tid < 168) {
        int d = tid - 144;
        float s = 0;
#pragma unroll 4
        for (int n = 0; n < 128; n++) { float q = qs[d][n]; s = fmaf(q, q, s); }
        out[576 + d] = s;
    } else {
        int e = tid - 168;
        float s = 0;
#pragma unroll 4
        for (int n = 0; n < 128; n++) { float q = ks[e][n]; s = fmaf(q, q, s); }
        out[600 + e] = s;
    }
}

// ---------------------------------------------------------------------------
// K3: dwconv for v channels — 4 px/thread, float4 I/O.
// Grid (HH/4, DIM, BATCH), block 256: thread -> (row = bx*4 + tid/64, x0 = (tid%64)*4)
// ---------------------------------------------------------------------------
__global__ __launch_bounds__(256)
void dwv_k(const float* __restrict__ qkv, const float* __restrict__ dww,
           float* __restrict__ v)
{
    const int b = blockIdx.z, c = blockIdx.y;
    const int tid = threadIdx.x;
    const int y = blockIdx.x * 4 + (tid >> 6);
    const int x0 = (tid & 63) * 4;
    const int ch = 384 + c;
    const float* in = qkv + ((size_t)(b * QKV_CH + ch) << 16);

    float w9[9];
#pragma unroll
    for (int i = 0; i < 9; i++) w9[i] = __ldg(dww + ch * 9 + i);

    float a0 = 0.f, a1 = 0.f, a2 = 0.f, a3 = 0.f;
#pragma unroll
    for (int dy = -1; dy <= 1; dy++) {
        int yy = y + dy;
        if (yy < 0 || yy > HH - 1) continue;
        const float* r = in + yy * WW;
        float4 m = *(const float4*)(r + x0);
        float left  = (x0 > 0)        ? __ldg(r + x0 - 1) : 0.f;
        float right = (x0 < WW - 4)   ? __ldg(r + x0 + 4) : 0.f;
        const float w0 = w9[(dy + 1) * 3 + 0];
        const float w1 = w9[(dy + 1) * 3 + 1];
        const float w2 = w9[(dy + 1) * 3 + 2];
        a0 = fmaf(w0, left, fmaf(w1, m.x, fmaf(w2, m.y, a0)));
        a1 = fmaf(w0, m.x,  fmaf(w1, m.y, fmaf(w2, m.z, a1)));
        a2 = fmaf(w0, m.y,  fmaf(w1, m.z, fmaf(w2, m.w, a2)));
        a3 = fmaf(w0, m.z,  fmaf(w1, m.w, fmaf(w2, right, a3)));
    }
    *(float4*)&v[((size_t)(b * DIM + c) << 16) + y * WW + x0] =
        make_float4(a0, a1, a2, a3);
}

// ---------------------------------------------------------------------------
// K4: reduce the 512 Gram partials per (b,head)
// ---------------------------------------------------------------------------
__global__ __launch_bounds__(624)
void reduce_k(const float* __restrict__ spart, float* __restrict__ sred)
{
    const int bh = blockIdx.x;
    const int j = threadIdx.x;
    const float* p = spart + (size_t)bh * 512 * 624 + j;
    float s = 0.f;
    for (int y = 0; y < 512; y++) s += p[(size_t)y * 624];
    sred[bh * 624 + j] = s;
}

// ---------------------------------------------------------------------------
// K5: softmax
// ---------------------------------------------------------------------------
__global__ __launch_bounds__(576)
void softmax_k(const float* __restrict__ sred, const float* __restrict__ temp,
               float* __restrict__ attn)
{
    const int bh = blockIdx.x;
    const int h = bh & 7;
    const int t = threadIdx.x;
    const int d = t / 24, e = t % 24;

    __shared__ float lg[24][24];
    __shared__ float rmax[24], rsum[24];

    const float* S = sred + bh * 624;
    float nq = fmaxf(sqrtf(S[576 + d]), 1e-12f);
    float nk = fmaxf(sqrtf(S[600 + e]), 1e-12f);
    float l = S[d * 24 + e] / (nq * nk) * temp[h];
    lg[d][e] = l;
    __syncthreads();

    if (e == 0) {
        float m = -1e30f;
        for (int j = 0; j < 24; j++) m = fmaxf(m, lg[d][j]);
        rmax[d] = m;
    }
    __syncthreads();
    float ex = expf(l - rmax[d]);
    lg[d][e] = ex;
    __syncthreads();
    if (e == 0) {
        float s = 0.f;
        for (int j = 0; j < 24; j++) s += lg[d][j];
        rsum[d] = s;
    }
    __syncthreads();
    attn[bh * 576 + d * 24 + e] = ex / rsum[d];
}

// ---------------------------------------------------------------------------
// K6: M[b] = P * blockdiag(attn[b]) -> extended bf16 rows
// ---------------------------------------------------------------------------
__global__ __launch_bounds__(256)
void buildM_k(const float* __restrict__ attn, const float* __restrict__ P,
              uint32_t* __restrict__ Mext)
{
    const int b = blockIdx.x;
    __shared__ float at[HEADS * 576];
    for (int i = threadIdx.x; i < HEADS * 576; i += 256) at[i] = attn[b * HEADS * 576 + i];
    __syncthreads();

    for (int idx = threadIdx.x; idx < DIM * DIM; idx += 256) {
        int o = idx / DIM, c = idx % DIM;
        int hh = c / 24, e = c % 24;
        float s = 0.f;
#pragma unroll
        for (int d = 0; d < 24; d++)
            s = fmaf(P[o * DIM + hh * 24 + d], at[hh * 576 + d * 24 + e], s);
        uint16_t h, l;
        split_bf16(s, h, l);
        uint16_t* row = (uint16_t*)(Mext + (size_t)b * WCHUNKE) + (size_t)o * KEXT;
        row[c] = h;
        row[192 + c] = l;
        row[384 + c] = h;
    }
}

// ---------------------------------------------------------------------------
// launch
// ---------------------------------------------------------------------------
extern "C" void kernel_launch(void* const* d_in, const int* in_sizes, int n_in,
                              void* d_out, int out_size)
{
    const float* x      = (const float*)d_in[0];
    const float* qkv_w  = (const float*)d_in[1];
    const float* dw_w   = (const float*)d_in[2];
    const float* proj_w = (const float*)d_in[3];
    const float* temp   = (const float*)d_in[4];
    float* out = (float*)d_out;

    float *qkv_s, *v_s, *spart, *sred, *attn;
    uint32_t *wext, *Mext;
    cudaGetSymbolAddress((void**)&qkv_s, g_qkv);
    cudaGetSymbolAddress((void**)&v_s,   g_v);
    cudaGetSymbolAddress((void**)&spart, g_spart);
    cudaGetSymbolAddress((void**)&sred,  g_sred);
    cudaGetSymbolAddress((void**)&attn,  g_attn);
    cudaGetSymbolAddress((void**)&wext,  g_wext);
    cudaGetSymbolAddress((void**)&Mext,  g_Mext);

    cudaFuncSetAttribute(tgemm_k, cudaFuncAttributeMaxDynamicSharedMemorySize,
                         TGEMM_SMEM);

    // K0: weight split/extend
    wprep_k<<<(QKV_CH * DIM + 255) / 256, 256>>>(qkv_w, wext);

    // K1: qkv = W_qkv @ x  (tensor-core 3-term split, 3 chunks internal)
    {
        dim3 grid(HWN / 128, BATCH);
        tgemm_k<<<grid, 512, TGEMM_SMEM>>>(wext, x, qkv_s, 0,
                                           (size_t)DIM * HWN, (size_t)QKV_CH * HWN, 3);
    }
    // K2: fused dwconv(q,k) + Gram partials
    {
        dim3 grid(512, HEADS, BATCH);
        dwgram_k<<<grid, 192>>>(qkv_s, dw_w, spart);
    }
    // K3: dwconv(v), 4 px/thread
    {
        dim3 grid(HH / 4, DIM, BATCH);
        dwv_k<<<grid, 256>>>(qkv_s, dw_w, v_s);
    }
    // K4: reduce Gram partials
    reduce_k<<<BATCH * HEADS, 624>>>(spart, sred);
    // K5: softmax
    softmax_k<<<BATCH * HEADS, 576>>>(sred, temp, attn);
    // K6: M = P * blockdiag(attn) -> extended bf16
    buildM_k<<<BATCH, 256>>>(attn, proj_w, Mext);
    // K7: out = M @ V (fused attn*V + projection)
    {
        dim3 grid(HWN / 128, BATCH);
        tgemm_k<<<grid, 512, TGEMM_SMEM>>>(Mext, v_s, out, WCHUNKE,
                                           (size_t)DIM * HWN, (size_t)DIM * HWN, 1);
    }
}

// round 6
// speedup vs baseline: 1.4641x; 1.4641x over previous
#include <cuda_runtime.h>
#include <cuda_bf16.h>
#include <math.h>
#include <stdint.h>

// ---------------------------------------------------------------------------
// Problem shapes (fixed)
// ---------------------------------------------------------------------------
#define BATCH 4
#define DIM 192
#define HEADS 8
#define HDIM 24
#define HH 256
#define WW 256
#define HWN 65536
#define QKV_CH 576

#define KEXT 576                     // 3 regions x 192 bf16 slots
#define WROW 288                     // u32 words per extended weight row
#define WCHUNKE (192 * WROW)         // u32 words per 192-row weight chunk

// ---------------------------------------------------------------------------
// Scratch (device globals: allocation-free rule)
// ---------------------------------------------------------------------------
__device__ float g_qkv[(size_t)BATCH * QKV_CH * HWN];
__device__ float g_v[(size_t)BATCH * DIM * HWN];
__device__ float g_spart[(size_t)BATCH * HEADS * 512 * 624];
__device__ float g_sred[BATCH * HEADS * 624];
__device__ float g_attn[BATCH * HEADS * HDIM * HDIM];
__device__ uint32_t g_wext[3 * WCHUNKE];        // qkv weights, 3-term ext rows
__device__ uint32_t g_Mext[BATCH * WCHUNKE];    // proj*blockdiag(attn), ext rows

// ---------------------------------------------------------------------------
// helpers
// ---------------------------------------------------------------------------
__device__ __forceinline__ void split_bf16(float v, uint16_t& h, uint16_t& l) {
    __nv_bfloat16 bh = __float2bfloat16(v);
    float r = v - __bfloat162float(bh);
    __nv_bfloat16 bl = __float2bfloat16(r);
    h = __bfloat16_as_ushort(bh);
    l = __bfloat16_as_ushort(bl);
}

__device__ __forceinline__ void mma16816(float* c, const uint32_t* a, const uint32_t* b) {
    asm volatile(
        "mma.sync.aligned.m16n8k16.row.col.f32.bf16.bf16.f32 "
        "{%0,%1,%2,%3}, {%4,%5,%6,%7}, {%8,%9}, {%0,%1,%2,%3};"
        : "+f"(c[0]), "+f"(c[1]), "+f"(c[2]), "+f"(c[3])
        : "r"(a[0]), "r"(a[1]), "r"(a[2]), "r"(a[3]), "r"(b[0]), "r"(b[1]));
}

// ---------------------------------------------------------------------------
// K0: split qkv weights -> extended bf16 rows [576 rows][576 slots]
// slot k = hi, 192+k = lo, 384+k = hi
// ---------------------------------------------------------------------------
__global__ __launch_bounds__(256)
void wprep_k(const float* __restrict__ w, uint32_t* __restrict__ wext)
{
    int idx = blockIdx.x * 256 + threadIdx.x;
    if (idx >= QKV_CH * DIM) return;
    int r = idx / DIM, k = idx % DIM;
    uint16_t h, l;
    split_bf16(w[idx], h, l);
    uint16_t* row = (uint16_t*)wext + (size_t)r * KEXT;
    row[k] = h;
    row[192 + k] = l;
    row[384 + k] = h;
}

// ---------------------------------------------------------------------------
// tgemm (R4-proven version): C[m][px] = sum_c W[m][c]*src[c][px], 3-term split.
// Block: 512 threads (16 warps, 4x4), BM=192, BN=128 px, K_ext=576, grid.y=chunk.
// ---------------------------------------------------------------------------
#define AS_STR 20
#define BS_STR 100
#define TGEMM_SMEM ((192 * AS_STR + 2 * 128 * BS_STR) * 4)   // 117760 B

__global__ __launch_bounds__(512, 1)
void tgemm_k(const uint32_t* __restrict__ wext, const float* __restrict__ src,
             float* __restrict__ out, size_t wBS, size_t srcBS, size_t outBS)
{
    extern __shared__ uint32_t dsm[];
    uint32_t* As   = dsm;                        // [192][AS_STR]
    uint32_t* Bs_h = dsm + 192 * AS_STR;         // [128 px][BS_STR] (96 used)
    uint32_t* Bs_l = Bs_h + 128 * BS_STR;

    const int tid = threadIdx.x;
    const int wid = tid >> 5;
    const int lane = tid & 31;
    const int g = lane >> 2;
    const int tig = lane & 3;
    const int warpM = wid & 3;
    const int warpN = wid >> 2;

    const int p0 = blockIdx.x * 128;
    const int chunk = blockIdx.y;
    const int b = blockIdx.z;

    const uint32_t* wp = wext + (size_t)chunk * WCHUNKE + (size_t)b * wBS;
    const float* sp = src + (size_t)b * srcBS + p0;

    // ---- phase 1: convert pixel tile -> resident Bs_h / Bs_l
#pragma unroll
    for (int pass = 0; pass < 6; pass++) {
        int cpair = pass * 16 + wid;
        const float* r0 = sp + ((size_t)(2 * cpair) << 16);
        const float* r1 = sp + ((size_t)(2 * cpair + 1) << 16);
#pragma unroll
        for (int i = 0; i < 4; i++) {
            int px = lane + 32 * i;
            uint16_t h0, l0, h1, l1;
            split_bf16(__ldg(r0 + px), h0, l0);
            split_bf16(__ldg(r1 + px), h1, l1);
            Bs_h[px * BS_STR + cpair] = (uint32_t)h1 << 16 | h0;
            Bs_l[px * BS_STR + cpair] = (uint32_t)l1 << 16 | l0;
        }
    }

    float acc[3][4][4];
#pragma unroll
    for (int mt = 0; mt < 3; mt++)
#pragma unroll
        for (int nt = 0; nt < 4; nt++)
#pragma unroll
            for (int i = 0; i < 4; i++) acc[mt][nt][i] = 0.f;

    // A slab loader indices (192 rows x 16 u32 per slab)
    const int aM0 = tid >> 2;
    const int aM1 = 128 + (tid >> 2);
    const int aJ = (tid & 3) * 4;

    uint4 apf0, apf1;
    apf0 = *(const uint4*)(wp + (size_t)aM0 * WROW + aJ);
    if (tid < 256) apf1 = *(const uint4*)(wp + (size_t)aM1 * WROW + aJ);
    __syncthreads();   // Bs ready

    for (int it = 0; it < 18; it++) {
        // store A slab
        *(uint4*)&As[aM0 * AS_STR + aJ] = apf0;
        if (tid < 256) *(uint4*)&As[aM1 * AS_STR + aJ] = apf1;
        __syncthreads();

        // prefetch next slab
        if (it < 17) {
            const uint32_t* wpn = wp + (it + 1) * 16;
            apf0 = *(const uint4*)(wpn + (size_t)aM0 * WROW + aJ);
            if (tid < 256) apf1 = *(const uint4*)(wpn + (size_t)aM1 * WROW + aJ);
        }

        const uint32_t* BsR = (it < 12) ? Bs_h : Bs_l;
        const int bbase = (it % 6) * 16;

#pragma unroll
        for (int ks = 0; ks < 2; ks++) {
            const int kc = ks * 8;
            uint32_t afr[3][4], bfr[4][2];
#pragma unroll
            for (int mt = 0; mt < 3; mt++) {
                int r0 = warpM * 48 + mt * 16 + g;
                afr[mt][0] = As[r0 * AS_STR + kc + tig];
                afr[mt][1] = As[(r0 + 8) * AS_STR + kc + tig];
                afr[mt][2] = As[r0 * AS_STR + kc + 4 + tig];
                afr[mt][3] = As[(r0 + 8) * AS_STR + kc + 4 + tig];
            }
#pragma unroll
            for (int nt = 0; nt < 4; nt++) {
                int n = warpN * 32 + nt * 8 + g;
                bfr[nt][0] = BsR[n * BS_STR + bbase + kc + tig];
                bfr[nt][1] = BsR[n * BS_STR + bbase + kc + 4 + tig];
            }
#pragma unroll
            for (int mt = 0; mt < 3; mt++)
#pragma unroll
                for (int nt = 0; nt < 4; nt++)
                    mma16816(acc[mt][nt], afr[mt], bfr[nt]);
        }
        __syncthreads();
    }

    // ---- epilogue
    float* op = out + (size_t)b * outBS + ((size_t)chunk * 192 << 16);
#pragma unroll
    for (int mt = 0; mt < 3; mt++) {
#pragma unroll
        for (int nt = 0; nt < 4; nt++) {
            int row = warpM * 48 + mt * 16 + g;
            int col = p0 + warpN * 32 + nt * 8 + tig * 2;
            *(float2*)&op[((size_t)row << 16) + col] =
                make_float2(acc[mt][nt][0], acc[mt][nt][1]);
            *(float2*)&op[((size_t)(row + 8) << 16) + col] =
                make_float2(acc[mt][nt][2], acc[mt][nt][3]);
        }
    }
}

// ---------------------------------------------------------------------------
// K2: fused dwconv (q,k) + Gram partials + norms — vectorized both phases.
// Grid: (512 half-rows, 8 heads, 4 batch).  Block: 192 threads.
// Load phase: 4 px/unit via float4 (dwv-style).  Gram: float4 over n.
// ---------------------------------------------------------------------------
__global__ __launch_bounds__(192)
void dwgram_k(const float* __restrict__ qkv, const float* __restrict__ dww,
              float* __restrict__ spart)
{
    __shared__ float qs[24][132];
    __shared__ float ks[24][132];

    const int b = blockIdx.z, h = blockIdx.y;
    const int y = blockIdx.x >> 1;
    const int x0 = (blockIdx.x & 1) * 128;
    const int tid = threadIdx.x;

    // ---- load phase: 48 ch x 32 units of 4 px = 1536 units, 8 per thread
    for (int u = tid; u < 48 * 32; u += 192) {
        int c = u >> 5;
        int xu = u & 31;
        int xg = x0 + xu * 4;
        int ch = (c < 24) ? (h * 24 + c) : (192 + h * 24 + (c - 24));
        const float* in = qkv + ((size_t)(b * QKV_CH + ch) << 16);
        const float* w9 = dww + ch * 9;
        float a0 = 0.f, a1 = 0.f, a2 = 0.f, a3 = 0.f;
#pragma unroll
        for (int dy = -1; dy <= 1; dy++) {
            int yy = y + dy;
            if (yy < 0 || yy > HH - 1) continue;
            const float* r = in + yy * WW;
            float4 m = *(const float4*)(r + xg);
            float left  = (xg > 0)      ? __ldg(r + xg - 1) : 0.f;
            float right = (xg < WW - 4) ? __ldg(r + xg + 4) : 0.f;
            float w0 = __ldg(w9 + (dy + 1) * 3 + 0);
            float w1 = __ldg(w9 + (dy + 1) * 3 + 1);
            float w2 = __ldg(w9 + (dy + 1) * 3 + 2);
            a0 = fmaf(w0, left, fmaf(w1, m.x, fmaf(w2, m.y, a0)));
            a1 = fmaf(w0, m.x,  fmaf(w1, m.y, fmaf(w2, m.z, a1)));
            a2 = fmaf(w0, m.y,  fmaf(w1, m.z, fmaf(w2, m.w, a2)));
            a3 = fmaf(w0, m.z,  fmaf(w1, m.w, fmaf(w2, right, a3)));
        }
        float* dst = (c < 24) ? &qs[c][xu * 4] : &ks[c - 24][xu * 4];
        *(float4*)dst = make_float4(a0, a1, a2, a3);
    }
    __syncthreads();

    float* out = spart + ((size_t)(b * HEADS + h) * 512 + blockIdx.x) * 624;

    if (tid < 144) {
        int d = (tid / 12) * 2, e = (tid % 12) * 2;
        float a00 = 0, a01 = 0, a10 = 0, a11 = 0;
#pragma unroll 4
        for (int n = 0; n < 128; n += 4) {
            float4 q0 = *(const float4*)&qs[d][n];
            float4 q1 = *(const float4*)&qs[d + 1][n];
            float4 k0 = *(const float4*)&ks[e][n];
            float4 k1 = *(const float4*)&ks[e + 1][n];
            a00 = fmaf(q0.x, k0.x, fmaf(q0.y, k0.y, fmaf(q0.z, k0.z, fmaf(q0.w, k0.w, a00))));
            a01 = fmaf(q0.x, k1.x, fmaf(q0.y, k1.y, fmaf(q0.z, k1.z, fmaf(q0.w, k1.w, a01))));
            a10 = fmaf(q1.x, k0.x, fmaf(q1.y, k0.y, fmaf(q1.z, k0.z, fmaf(q1.w, k0.w, a10))));
            a11 = fmaf(q1.x, k1.x, fmaf(q1.y, k1.y, fmaf(q1.z, k1.z, fmaf(q1.w, k1.w, a11))));
        }
        out[d * 24 + e] = a00;
        out[d * 24 + e + 1] = a01;
        out[(d + 1) * 24 + e] = a10;
        out[(d + 1) * 24 + e + 1] = a11;
    } else if (tid < 168) {
        int d = tid - 144;
        float s = 0;
#pragma unroll 4
        for (int n = 0; n < 128; n += 4) {
            float4 q = *(const float4*)&qs[d][n];
            s = fmaf(q.x, q.x, fmaf(q.y, q.y, fmaf(q.z, q.z, fmaf(q.w, q.w, s))));
        }
        out[576 + d] = s;
    } else {
        int e = tid - 168;
        float s = 0;
#pragma unroll 4
        for (int n = 0; n < 128; n += 4) {
            float4 q = *(const float4*)&ks[e][n];
            s = fmaf(q.x, q.x, fmaf(q.y, q.y, fmaf(q.z, q.z, fmaf(q.w, q.w, s))));
        }
        out[600 + e] = s;
    }
}

// ---------------------------------------------------------------------------
// K3: dwconv for v channels — 4 px/thread, float4 I/O (R5-proven).
// ---------------------------------------------------------------------------
__global__ __launch_bounds__(256)
void dwv_k(const float* __restrict__ qkv, const float* __restrict__ dww,
           float* __restrict__ v)
{
    const int b = blockIdx.z, c = blockIdx.y;
    const int tid = threadIdx.x;
    const int y = blockIdx.x * 4 + (tid >> 6);
    const int x0 = (tid & 63) * 4;
    const int ch = 384 + c;
    const float* in = qkv + ((size_t)(b * QKV_CH + ch) << 16);

    float w9[9];
#pragma unroll
    for (int i = 0; i < 9; i++) w9[i] = __ldg(dww + ch * 9 + i);

    float a0 = 0.f, a1 = 0.f, a2 = 0.f, a3 = 0.f;
#pragma unroll
    for (int dy = -1; dy <= 1; dy++) {
        int yy = y + dy;
        if (yy < 0 || yy > HH - 1) continue;
        const float* r = in + yy * WW;
        float4 m = *(const float4*)(r + x0);
        float left  = (x0 > 0)        ? __ldg(r + x0 - 1) : 0.f;
        float right = (x0 < WW - 4)   ? __ldg(r + x0 + 4) : 0.f;
        const float w0 = w9[(dy + 1) * 3 + 0];
        const float w1 = w9[(dy + 1) * 3 + 1];
        const float w2 = w9[(dy + 1) * 3 + 2];
        a0 = fmaf(w0, left, fmaf(w1, m.x, fmaf(w2, m.y, a0)));
        a1 = fmaf(w0, m.x,  fmaf(w1, m.y, fmaf(w2, m.z, a1)));
        a2 = fmaf(w0, m.y,  fmaf(w1, m.z, fmaf(w2, m.w, a2)));
        a3 = fmaf(w0, m.z,  fmaf(w1, m.w, fmaf(w2, right, a3)));
    }
    *(float4*)&v[((size_t)(b * DIM + c) << 16) + y * WW + x0] =
        make_float4(a0, a1, a2, a3);
}

// ---------------------------------------------------------------------------
// K4: reduce the 512 Gram partials per (b,head)
// ---------------------------------------------------------------------------
__global__ __launch_bounds__(624)
void reduce_k(const float* __restrict__ spart, float* __restrict__ sred)
{
    const int bh = blockIdx.x;
    const int j = threadIdx.x;
    const float* p = spart + (size_t)bh * 512 * 624 + j;
    float s = 0.f;
    for (int y = 0; y < 512; y++) s += p[(size_t)y * 624];
    sred[bh * 624 + j] = s;
}

// ---------------------------------------------------------------------------
// K5: softmax
// ---------------------------------------------------------------------------
__global__ __launch_bounds__(576)
void softmax_k(const float* __restrict__ sred, const float* __restrict__ temp,
               float* __restrict__ attn)
{
    const int bh = blockIdx.x;
    const int h = bh & 7;
    const int t = threadIdx.x;
    const int d = t / 24, e = t % 24;

    __shared__ float lg[24][24];
    __shared__ float rmax[24], rsum[24];

    const float* S = sred + bh * 624;
    float nq = fmaxf(sqrtf(S[576 + d]), 1e-12f);
    float nk = fmaxf(sqrtf(S[600 + e]), 1e-12f);
    float l = S[d * 24 + e] / (nq * nk) * temp[h];
    lg[d][e] = l;
    __syncthreads();

    if (e == 0) {
        float m = -1e30f;
        for (int j = 0; j < 24; j++) m = fmaxf(m, lg[d][j]);
        rmax[d] = m;
    }
    __syncthreads();
    float ex = expf(l - rmax[d]);
    lg[d][e] = ex;
    __syncthreads();
    if (e == 0) {
        float s = 0.f;
        for (int j = 0; j < 24; j++) s += lg[d][j];
        rsum[d] = s;
    }
    __syncthreads();
    attn[bh * 576 + d * 24 + e] = ex / rsum[d];
}

// ---------------------------------------------------------------------------
// K6: M[b] = P * blockdiag(attn[b]) -> extended bf16 rows
// ---------------------------------------------------------------------------
__global__ __launch_bounds__(256)
void buildM_k(const float* __restrict__ attn, const float* __restrict__ P,
              uint32_t* __restrict__ Mext)
{
    const int b = blockIdx.x;
    __shared__ float at[HEADS * 576];
    for (int i = threadIdx.x; i < HEADS * 576; i += 256) at[i] = attn[b * HEADS * 576 + i];
    __syncthreads();

    for (int idx = threadIdx.x; idx < DIM * DIM; idx += 256) {
        int o = idx / DIM, c = idx % DIM;
        int hh = c / 24, e = c % 24;
        float s = 0.f;
#pragma unroll
        for (int d = 0; d < 24; d++)
            s = fmaf(P[o * DIM + hh * 24 + d], at[hh * 576 + d * 24 + e], s);
        uint16_t h, l;
        split_bf16(s, h, l);
        uint16_t* row = (uint16_t*)(Mext + (size_t)b * WCHUNKE) + (size_t)o * KEXT;
        row[c] = h;
        row[192 + c] = l;
        row[384 + c] = h;
    }
}

// ---------------------------------------------------------------------------
// launch
// ---------------------------------------------------------------------------
extern "C" void kernel_launch(void* const* d_in, const int* in_sizes, int n_in,
                              void* d_out, int out_size)
{
    const float* x      = (const float*)d_in[0];
    const float* qkv_w  = (const float*)d_in[1];
    const float* dw_w   = (const float*)d_in[2];
    const float* proj_w = (const float*)d_in[3];
    const float* temp   = (const float*)d_in[4];
    float* out = (float*)d_out;

    float *qkv_s, *v_s, *spart, *sred, *attn;
    uint32_t *wext, *Mext;
    cudaGetSymbolAddress((void**)&qkv_s, g_qkv);
    cudaGetSymbolAddress((void**)&v_s,   g_v);
    cudaGetSymbolAddress((void**)&spart, g_spart);
    cudaGetSymbolAddress((void**)&sred,  g_sred);
    cudaGetSymbolAddress((void**)&attn,  g_attn);
    cudaGetSymbolAddress((void**)&wext,  g_wext);
    cudaGetSymbolAddress((void**)&Mext,  g_Mext);

    cudaFuncSetAttribute(tgemm_k, cudaFuncAttributeMaxDynamicSharedMemorySize,
                         TGEMM_SMEM);

    // K0: weight split/extend
    wprep_k<<<(QKV_CH * DIM + 255) / 256, 256>>>(qkv_w, wext);

    // K1: qkv = W_qkv @ x  (tensor-core 3-term split, chunks in grid.y)
    {
        dim3 grid(HWN / 128, 3, BATCH);
        tgemm_k<<<grid, 512, TGEMM_SMEM>>>(wext, x, qkv_s, 0,
                                           (size_t)DIM * HWN, (size_t)QKV_CH * HWN);
    }
    // K2: fused dwconv(q,k) + Gram partials (vectorized)
    {
        dim3 grid(512, HEADS, BATCH);
        dwgram_k<<<grid, 192>>>(qkv_s, dw_w, spart);
    }
    // K3: dwconv(v), 4 px/thread
    {
        dim3 grid(HH / 4, DIM, BATCH);
        dwv_k<<<grid, 256>>>(qkv_s, dw_w, v_s);
    }
    // K4: reduce Gram partials
    reduce_k<<<BATCH * HEADS, 624>>>(spart, sred);
    // K5: softmax
    softmax_k<<<BATCH * HEADS, 576>>>(sred, temp, attn);
    // K6: M = P * blockdiag(attn) -> extended bf16
    buildM_k<<<BATCH, 256>>>(attn, proj_w, Mext);
    // K7: out = M @ V (fused attn*V + projection)
    {
        dim3 grid(HWN / 128, 1, BATCH);
        tgemm_k<<<grid, 512, TGEMM_SMEM>>>(Mext, v_s, out, WCHUNKE,
                                           (size_t)DIM * HWN, (size_t)DIM * HWN);
    }
}